// round 6
// baseline (speedup 1.0000x reference)
#include <cuda_runtime.h>
#include <math.h>
#include <stdint.h>

// ===========================================================================
// KnotAttention via mma.sync tf32, NT=64, double-buffered W cp.async pipeline,
// interleaved k-columns for LDS.64 fragment loads.
//  prep: W images [slot][n][q(d)] tf32-rounded (k-interleaved)
//  E:    per tile: Q=A0@Wq; per r: K_r=A_r@Wk_r; E=exp(QK/sqrt32); partials
//  R:    reduce partials -> 1/denominator (softmax over NODE axis)
//  O:    per r: V_r=A_r@Wv_r; acc += (E*Sinv)*V_r; write out
// ===========================================================================

#define NT       64
#define THREADS  256
#define MAXN     131072
#define MAXTILES (MAXN / NT)
#define SCALE    0.17677669529663687f   // 1/sqrt(32)
#define AS2      136                    // smem row stride (floats); 136%32==8
#define A_FLOATS (NT * AS2)             // 8704
#define W_FLOATS (128 * AS2)            // 17408
#define SMEM_SZ  ((A_FLOATS + 2 * W_FLOATS) * 4)   // 174080 B -> 1 CTA/SM

__device__ float g_E[(size_t)20 * MAXN];
__device__ float g_part[20 * MAXTILES];
__device__ float g_Sinv[20];
__device__ int   g_is64;
__device__ float g_Wt[11 * 128 * 128];  // [slot][n][q(d)], tf32-rounded

// -------- helpers --------
__device__ __forceinline__ uint32_t smem_u32(const void* p) {
    uint32_t a;
    asm("{ .reg .u64 t; cvta.to.shared.u64 t, %1; cvt.u32.u64 %0, t; }" : "=r"(a) : "l"(p));
    return a;
}
__device__ __forceinline__ void cpa16(uint32_t s, const void* g) {
    asm volatile("cp.async.cg.shared.global [%0], [%1], 16;" :: "r"(s), "l"(g) : "memory");
}
__device__ __forceinline__ void cpa4(uint32_t s, const void* g) {
    asm volatile("cp.async.ca.shared.global [%0], [%1], 4;" :: "r"(s), "l"(g) : "memory");
}
__device__ __forceinline__ void cpa_commit() {
    asm volatile("cp.async.commit_group;" ::: "memory");
}
__device__ __forceinline__ void cpa_wait1() {
    asm volatile("cp.async.wait_group 1;" ::: "memory");
}
__device__ __forceinline__ void cpa_wait0() {
    asm volatile("cp.async.wait_group 0;" ::: "memory");
}
__device__ __forceinline__ uint32_t f2tf(float x) {
    uint32_t u;
    asm("cvt.rna.tf32.f32 %0, %1;" : "=r"(u) : "f"(x));
    return u;
}
__device__ __forceinline__ void mma8(float* c, uint32_t a0, uint32_t a1, uint32_t a2,
                                     uint32_t a3, uint32_t b0, uint32_t b1) {
    asm volatile(
        "mma.sync.aligned.m16n8k8.row.col.f32.tf32.tf32.f32 "
        "{%0,%1,%2,%3}, {%4,%5,%6,%7}, {%8,%9}, {%0,%1,%2,%3};"
        : "+f"(c[0]), "+f"(c[1]), "+f"(c[2]), "+f"(c[3])
        : "r"(a0), "r"(a1), "r"(a2), "r"(a3), "r"(b0), "r"(b1));
}
__device__ __forceinline__ int qperm(int k) {   // interleave within 8-col groups
    return (k & ~7) | ((k & 3) << 1) | ((k >> 2) & 1);
}

// -------- prep: weight images [slot][n][q(d)], tf32-rounded --------
__global__ void knot_prep(const float* __restrict__ wq, const float* __restrict__ wk,
                          const float* __restrict__ wv)
{
    int slot = blockIdx.x;
    float* dst = g_Wt + slot * 16384;
    for (int i = 0; i < 64; ++i) {
        int f = threadIdx.x + 256 * i;     // 0..16383
        int n = f >> 7, d = f & 127;
        int h = n >> 5, k = n & 31;
        float v;
        if (slot == 0)      v = wq[((size_t)h * 128 + d) * 32 + k];
        else if (slot <= 5) v = wk[(((size_t)(h * 5 + (slot - 1)) * 128) + d) * 32 + k];
        else                v = wv[(((size_t)(h * 5 + (slot - 6)) * 128) + d) * 32 + k];
        dst[n * 128 + qperm(d)] = __uint_as_float(f2tf(v));
    }
}

__global__ void knot_detect(const int* __restrict__ nbr_i32)
{
    if (threadIdx.x == 0 && blockIdx.x == 0) {
        int any = 0;
        #pragma unroll
        for (int i = 1; i < 64; i += 2) any |= nbr_i32[i];
        g_is64 = (any == 0) ? 1 : 0;
    }
}

// -------- staging --------
// A: 64 rows x 128 cols, k-interleaved via 4B cp.async. Warp w owns rows w*8..+7.
__device__ __forceinline__ void stage_A(float* sA, const float* __restrict__ x,
                                        const void* __restrict__ nbr, int is64,
                                        int n0, int r, int N)
{
    const int w = threadIdx.x >> 5, l = threadIdx.x & 31;
    #pragma unroll
    for (int rr = 0; rr < 8; ++rr) {
        int row = w * 8 + rr;
        int n = n0 + row;
        int nc = (n < N) ? n : 0;
        long long src;
        if (r == 0) src = nc;
        else {
            long long e = (long long)nc * 4 + (r - 1);
            src = is64 ? __ldg((const long long*)nbr + e)
                       : (long long)__ldg((const int*)nbr + e);
        }
        if (src < 0) src = 0;
        if (src >= N) src = N - 1;
        const float* srcp = x + (size_t)src * 128;
        #pragma unroll
        for (int kk = 0; kk < 4; ++kk) {
            int k = kk * 32 + l;
            cpa4(smem_u32(sA + row * AS2 + qperm(k)), srcp + k);
        }
    }
}
// W: copy pre-permuted image rows (128 x 512B) into stride-AS2 smem
__device__ __forceinline__ void stage_W(float* sW, int slot)
{
    const float* src = g_Wt + slot * 16384;
    int t = threadIdx.x;
    #pragma unroll
    for (int i = 0; i < 16; ++i) {
        int f = t + 256 * i;               // 4096 chunks of 16B
        int row = f >> 5, c4 = f & 31;
        cpa16(smem_u32(sW + row * AS2 + c4 * 4), src + row * 128 + c4 * 4);
    }
}

// -------- warp GEMM: per-warp 32x32 block of A(64x128) @ W^T --------
__device__ __forceinline__ void gemm64(const float* sA, const float* sW,
                                       int wm, int wn, int g, int t4,
                                       float C[2][4][4])
{
    #pragma unroll
    for (int ks = 0; ks < 16; ++ks) {
        uint32_t a[2][4];
        #pragma unroll
        for (int mt = 0; mt < 2; ++mt) {
            const float* base = sA + (wm * 32 + mt * 16 + g) * AS2 + ks * 8 + 2 * t4;
            float2 lo = *(const float2*)base;
            float2 hi = *(const float2*)(base + 8 * AS2);
            a[mt][0] = f2tf(lo.x);  a[mt][2] = f2tf(lo.y);
            a[mt][1] = f2tf(hi.x);  a[mt][3] = f2tf(hi.y);
        }
        #pragma unroll
        for (int nt = 0; nt < 4; ++nt) {
            float2 b = *(const float2*)(sW + (wn * 32 + nt * 8 + g) * AS2 + ks * 8 + 2 * t4);
            uint32_t b0 = __float_as_uint(b.x), b1 = __float_as_uint(b.y);
            mma8(C[0][nt], a[0][0], a[0][1], a[0][2], a[0][3], b0, b1);
            mma8(C[1][nt], a[1][0], a[1][1], a[1][2], a[1][3], b0, b1);
        }
    }
}

#define ZERO_C(C)                                                   \
    _Pragma("unroll") for (int mt = 0; mt < 2; ++mt)                \
    _Pragma("unroll") for (int nt = 0; nt < 4; ++nt)                \
    _Pragma("unroll") for (int ci = 0; ci < 4; ++ci) C[mt][nt][ci] = 0.f;

// -------- kernel E --------
__global__ __launch_bounds__(THREADS, 1)
void knot_E(const float* __restrict__ x, const void* __restrict__ nbr, int N)
{
    extern __shared__ float smf[];
    float* sA  = smf;
    float* sW0 = smf + A_FLOATS;
    float* sW1 = sW0 + W_FLOATS;
    float* sWb[2] = { sW0, sW1 };
    __shared__ float warr[8];

    const int t = threadIdx.x, w = t >> 5, l = t & 31;
    const int wm = w >> 2, wn = w & 3, g = l >> 2, t4 = l & 3;
    const int tile = blockIdx.x, n0 = tile * NT;
    const int is64 = g_is64;
    const int h = wn;

    // prologue: Wq, A0, Wk0
    stage_W(sW0, 0); cpa_commit();
    stage_A(sA, x, nbr, is64, n0, 0, N); cpa_commit();
    stage_W(sW1, 1); cpa_commit();

    // ---- slot 0: Q ----
    float qC[2][4][4]; ZERO_C(qC);
    cpa_wait1();
    __syncthreads();
    gemm64(sA, sW0, wm, wn, g, t4, qC);
    __syncthreads();
    stage_W(sW0, 2); cpa_commit();       // slot 2 into buf0

    // ---- slots 1..5: K_r, r = 0..4 (K_0 reuses A0) ----
    for (int r = 0; r < 5; ++r) {
        if (r < 4) cpa_wait1(); else cpa_wait0();
        __syncthreads();

        float kC[2][4][4]; ZERO_C(kC);
        gemm64(sA, sWb[(r + 1) & 1], wm, wn, g, t4, kC);

        // ---- logits, exp, E store, partial sums (head h = wn) ----
        float hs = 0.f;
        #pragma unroll
        for (int mt = 0; mt < 2; ++mt) {
            #pragma unroll
            for (int rr2 = 0; rr2 < 2; ++rr2) {
                int n = n0 + wm * 32 + mt * 16 + g + rr2 * 8;
                float ds = 0.f;
                #pragma unroll
                for (int nt = 0; nt < 4; ++nt) {
                    ds = fmaf(qC[mt][nt][rr2 * 2],     kC[mt][nt][rr2 * 2],     ds);
                    ds = fmaf(qC[mt][nt][rr2 * 2 + 1], kC[mt][nt][rr2 * 2 + 1], ds);
                }
                ds += __shfl_xor_sync(0xFFFFFFFFu, ds, 1);
                ds += __shfl_xor_sync(0xFFFFFFFFu, ds, 2);
                if (t4 == 0) {
                    float e = 0.f;
                    if (n < N) {
                        e = __expf(ds * SCALE);
                        g_E[(size_t)(h * 5 + r) * N + n] = e;
                    }
                    hs += e;
                }
            }
        }
        #pragma unroll
        for (int o = 16; o > 0; o >>= 1)
            hs += __shfl_down_sync(0xFFFFFFFFu, hs, o);
        if (l == 0) warr[w] = hs;
        __syncthreads();
        if (t < 4)
            g_part[(t * 5 + r) * MAXTILES + tile] = warr[t] + warr[4 + t];
        __syncthreads();                  // all smem reads of this slot done

        if (r + 1 < 5) { stage_A(sA, x, nbr, is64, n0, r + 1, N); cpa_commit(); }
        if (r + 3 <= 5) { stage_W(sWb[(r + 1) & 1], r + 3); cpa_commit(); }
    }
}

// -------- kernel R --------
__global__ void knot_R(int cnt)
{
    __shared__ float smr[256];
    const int b = blockIdx.x;
    float s = 0.f;
    for (int i = threadIdx.x; i < cnt; i += 256) s += g_part[b * MAXTILES + i];
    smr[threadIdx.x] = s;
    __syncthreads();
    for (int off = 128; off > 0; off >>= 1) {
        if (threadIdx.x < off) smr[threadIdx.x] += smr[threadIdx.x + off];
        __syncthreads();
    }
    if (threadIdx.x == 0) g_Sinv[b] = 1.0f / smr[0];
}

// -------- kernel O --------
__global__ __launch_bounds__(THREADS, 1)
void knot_O(const float* __restrict__ x, const void* __restrict__ nbr,
            float* __restrict__ out, int N)
{
    extern __shared__ float smf[];
    float* sA  = smf;
    float* sW0 = smf + A_FLOATS;
    float* sW1 = sW0 + W_FLOATS;
    float* sWb[2] = { sW0, sW1 };

    const int t = threadIdx.x, w = t >> 5, l = t & 31;
    const int wm = w >> 2, wn = w & 3, g = l >> 2, t4 = l & 3;
    const int tile = blockIdx.x, n0 = tile * NT;
    const int is64 = g_is64;
    const int h = wn;

    stage_W(sW0, 6); cpa_commit();
    stage_A(sA, x, nbr, is64, n0, 0, N); cpa_commit();
    stage_W(sW1, 7); cpa_commit();

    float acc[2][4][4]; ZERO_C(acc);

    for (int r = 0; r < 5; ++r) {
        if (r < 4) cpa_wait1(); else cpa_wait0();
        __syncthreads();

        float C[2][4][4]; ZERO_C(C);
        gemm64(sA, sWb[r & 1], wm, wn, g, t4, C);

        float av[2][2];
        const float si = g_Sinv[h * 5 + r];
        #pragma unroll
        for (int mt = 0; mt < 2; ++mt)
            #pragma unroll
            for (int rr2 = 0; rr2 < 2; ++rr2) {
                int n = n0 + wm * 32 + mt * 16 + g + rr2 * 8;
                av[mt][rr2] = (n < N)
                    ? __ldg(&g_E[(size_t)(h * 5 + r) * N + n]) * si : 0.f;
            }
        #pragma unroll
        for (int mt = 0; mt < 2; ++mt)
            #pragma unroll
            for (int nt = 0; nt < 4; ++nt)
                #pragma unroll
                for (int ci = 0; ci < 4; ++ci)
                    acc[mt][nt][ci] = fmaf(av[mt][ci >> 1], C[mt][nt][ci],
                                           acc[mt][nt][ci]);
        __syncthreads();                  // smem reads done before restage

        if (r + 1 <= 4) { stage_A(sA, x, nbr, is64, n0, r + 1, N); cpa_commit(); }
        if (r + 2 <= 4) { stage_W(sWb[r & 1], 6 + r + 2); cpa_commit(); }
    }

    // ---- transpose via smem (A region), coalesced output ----
    #pragma unroll
    for (int mt = 0; mt < 2; ++mt)
        #pragma unroll
        for (int nt = 0; nt < 4; ++nt)
            #pragma unroll
            for (int ci = 0; ci < 4; ++ci) {
                int row = wm * 32 + mt * 16 + g + (ci >> 1) * 8;
                int col = wn * 32 + nt * 8 + t4 * 2 + (ci & 1);
                sA[row * AS2 + col] = acc[mt][nt][ci];
            }
    __syncthreads();
    #pragma unroll
    for (int i = 0; i < 8; ++i) {
        int f = t + 256 * i;
        int row = f >> 5, c4 = f & 31;
        int n = n0 + row;
        if (n < N)
            *(float4*)(out + (size_t)n * 128 + c4 * 4) =
                *(const float4*)(sA + row * AS2 + c4 * 4);
    }
}

extern "C" void kernel_launch(void* const* d_in, const int* in_sizes, int n_in,
                              void* d_out, int out_size)
{
    const float* x   = (const float*)d_in[0];
    const void*  nbr = d_in[1];
    const float* wq  = (const float*)d_in[2];
    const float* wk  = (const float*)d_in[3];
    const float* wv  = (const float*)d_in[4];
    float*       out = (float*)d_out;

    const int N   = in_sizes[0] / 128;
    const int NBT = (N + NT - 1) / NT;

    cudaFuncSetAttribute(knot_E, cudaFuncAttributeMaxDynamicSharedMemorySize, SMEM_SZ);
    cudaFuncSetAttribute(knot_O, cudaFuncAttributeMaxDynamicSharedMemorySize, SMEM_SZ);

    knot_detect<<<1, 32>>>((const int*)nbr);
    knot_prep<<<11, 256>>>(wq, wk, wv);
    knot_E<<<NBT, THREADS, SMEM_SZ>>>(x, nbr, N);
    knot_R<<<20, 256>>>(NBT);
    knot_O<<<NBT, THREADS, SMEM_SZ>>>(x, nbr, out, N);
}

// round 7
// speedup vs baseline: 1.2341x; 1.2341x over previous
#include <cuda_runtime.h>
#include <math.h>
#include <stdint.h>

// ===========================================================================
// KnotAttention via mma.sync tf32. NT=128 tiles, double-buffered W pipeline
// (A 128x132 + 2x W 128x136 = 206.8KB smem, 1 CTA/SM), cp.async 16B staging,
// fast-tf32 A operands (no cvt), prep-permuted W for LDS.64 B fragments.
//  E: per tile: Q=A0@Wq; per r: K_r=A_r@Wk_r; E=exp(QK/sqrt32); partials
//  R: reduce partials -> 1/denominator (softmax over NODE axis)
//  O: per r: V_r=A_r@Wv_r; acc += (E*Sinv)*V_r; write out
// ===========================================================================

#define NT       128
#define THREADS  256
#define MAXN     131072
#define MAXTILES (MAXN / NT)
#define SCALE    0.17677669529663687f   // 1/sqrt(32)
#define AS_A     132                    // A stride: conflict-free LDS.32 frags
#define AS_W     136                    // W stride: conflict-free LDS.64 frags
#define A_FLOATS (NT * AS_A)            // 16896
#define W_FLOATS (128 * AS_W)           // 17408
#define SMEM_SZ  ((A_FLOATS + 2 * W_FLOATS) * 4)   // 206848 B

__device__ float g_E[(size_t)20 * MAXN];
__device__ float g_part[20 * MAXTILES];
__device__ float g_Sinv[20];
__device__ int   g_is64;
__device__ float g_Wt[11 * 128 * 128];  // [slot][n][qperm(d)], tf32-rounded

// -------- helpers --------
__device__ __forceinline__ uint32_t smem_u32(const void* p) {
    uint32_t a;
    asm("{ .reg .u64 t; cvta.to.shared.u64 t, %1; cvt.u32.u64 %0, t; }" : "=r"(a) : "l"(p));
    return a;
}
__device__ __forceinline__ void cpa16(uint32_t s, const void* g) {
    asm volatile("cp.async.cg.shared.global [%0], [%1], 16;" :: "r"(s), "l"(g) : "memory");
}
__device__ __forceinline__ void cpa_commit() { asm volatile("cp.async.commit_group;" ::: "memory"); }
__device__ __forceinline__ void cpa_wait1()  { asm volatile("cp.async.wait_group 1;" ::: "memory"); }
__device__ __forceinline__ void cpa_wait0()  { asm volatile("cp.async.wait_group 0;" ::: "memory"); }
__device__ __forceinline__ uint32_t f2tf(float x) {
    uint32_t u;
    asm("cvt.rna.tf32.f32 %0, %1;" : "=r"(u) : "f"(x));
    return u;
}
__device__ __forceinline__ void mma8(float* c, uint32_t a0, uint32_t a1, uint32_t a2,
                                     uint32_t a3, uint32_t b0, uint32_t b1) {
    asm volatile(
        "mma.sync.aligned.m16n8k8.row.col.f32.tf32.tf32.f32 "
        "{%0,%1,%2,%3}, {%4,%5,%6,%7}, {%8,%9}, {%0,%1,%2,%3};"
        : "+f"(c[0]), "+f"(c[1]), "+f"(c[2]), "+f"(c[3])
        : "r"(a0), "r"(a1), "r"(a2), "r"(a3), "r"(b0), "r"(b1));
}
__device__ __forceinline__ int qperm(int k) {   // interleave within 8-col groups
    return (k & ~7) | ((k & 3) << 1) | ((k >> 2) & 1);
}

// -------- prep: weight images [slot][n][qperm(d)], tf32-rounded --------
__global__ void knot_prep(const float* __restrict__ wq, const float* __restrict__ wk,
                          const float* __restrict__ wv)
{
    int slot = blockIdx.x;
    float* dst = g_Wt + slot * 16384;
    for (int i = 0; i < 64; ++i) {
        int f = threadIdx.x + 256 * i;     // 0..16383
        int n = f >> 7, d = f & 127;
        int h = n >> 5, k = n & 31;
        float v;
        if (slot == 0)      v = wq[((size_t)h * 128 + d) * 32 + k];
        else if (slot <= 5) v = wk[(((size_t)(h * 5 + (slot - 1)) * 128) + d) * 32 + k];
        else                v = wv[(((size_t)(h * 5 + (slot - 6)) * 128) + d) * 32 + k];
        dst[n * 128 + qperm(d)] = __uint_as_float(f2tf(v));
    }
}

__global__ void knot_detect(const int* __restrict__ nbr_i32)
{
    if (threadIdx.x == 0 && blockIdx.x == 0) {
        int any = 0;
        #pragma unroll
        for (int i = 1; i < 64; i += 2) any |= nbr_i32[i];
        g_is64 = (any == 0) ? 1 : 0;
    }
}

// -------- staging (cp.async 16B only) --------
__device__ __forceinline__ void stage_A(float* sA, const float* __restrict__ x,
                                        const void* __restrict__ nbr, int is64,
                                        int n0, int r, int N)
{
    int t = threadIdx.x;
    #pragma unroll
    for (int i = 0; i < 16; ++i) {
        int f = t + 256 * i;               // 128 rows x 32 chunks
        int row = f >> 5, c4 = f & 31;
        int n = n0 + row;
        int nc = (n < N) ? n : 0;
        long long src;
        if (r == 0) src = nc;
        else {
            long long e = (long long)nc * 4 + (r - 1);
            src = is64 ? __ldg((const long long*)nbr + e)
                       : (long long)__ldg((const int*)nbr + e);
        }
        if (src < 0) src = 0;
        if (src >= N) src = N - 1;
        cpa16(smem_u32(sA + row * AS_A + c4 * 4), x + (size_t)src * 128 + c4 * 4);
    }
}
__device__ __forceinline__ void stage_W(float* sW, int slot)
{
    const float* src = g_Wt + slot * 16384;
    int t = threadIdx.x;
    #pragma unroll
    for (int i = 0; i < 16; ++i) {
        int f = t + 256 * i;
        int row = f >> 5, c4 = f & 31;
        cpa16(smem_u32(sW + row * AS_W + c4 * 4), src + row * 128 + c4 * 4);
    }
}

// -------- warp GEMM: 32(m) x 64(n) per warp; wm=w>>1 (0..3), wn=w&1 (0..1) ----
// A fragments: raw fp32 bits (fast tf32). B: LDS.64 from qperm'd W.
__device__ __forceinline__ void gemm128(const float* sA, const float* sW,
                                        int wm, int wn, int g, int t4,
                                        float C[2][8][4])
{
    #pragma unroll
    for (int ks = 0; ks < 16; ++ks) {
        uint32_t a[2][4];
        #pragma unroll
        for (int mt = 0; mt < 2; ++mt) {
            const float* ap = sA + (wm * 32 + mt * 16 + g) * AS_A + ks * 8 + t4;
            a[mt][0] = __float_as_uint(ap[0]);
            a[mt][1] = __float_as_uint(ap[8 * AS_A]);
            a[mt][2] = __float_as_uint(ap[4]);
            a[mt][3] = __float_as_uint(ap[8 * AS_A + 4]);
        }
        #pragma unroll
        for (int nt = 0; nt < 8; ++nt) {
            float2 b = *(const float2*)(sW + (wn * 64 + nt * 8 + g) * AS_W + ks * 8 + 2 * t4);
            uint32_t b0 = __float_as_uint(b.x), b1 = __float_as_uint(b.y);
            mma8(C[0][nt], a[0][0], a[0][1], a[0][2], a[0][3], b0, b1);
            mma8(C[1][nt], a[1][0], a[1][1], a[1][2], a[1][3], b0, b1);
        }
    }
}

#define ZERO_C(C)                                                   \
    _Pragma("unroll") for (int mt = 0; mt < 2; ++mt)                \
    _Pragma("unroll") for (int nt = 0; nt < 8; ++nt)                \
    _Pragma("unroll") for (int ci = 0; ci < 4; ++ci) C[mt][nt][ci] = 0.f;

// -------- kernel E --------
__global__ __launch_bounds__(THREADS, 1)
void knot_E(const float* __restrict__ x, const void* __restrict__ nbr, int N)
{
    extern __shared__ float smf[];
    float* sA  = smf;
    float* sW0 = smf + A_FLOATS;
    float* sW1 = sW0 + W_FLOATS;
    float* sWb[2] = { sW0, sW1 };
    __shared__ float warr[8][2];

    const int t = threadIdx.x, w = t >> 5, l = t & 31;
    const int wm = w >> 1, wn = w & 1, g = l >> 2, t4 = l & 3;
    const int tile = blockIdx.x, n0 = tile * NT;
    const int is64 = g_is64;

    // prologue
    stage_W(sW0, 0); cpa_commit();
    stage_A(sA, x, nbr, is64, n0, 0, N); cpa_commit();
    stage_W(sW1, 1); cpa_commit();

    // ---- Q (buf0) ----
    float qC[2][8][4]; ZERO_C(qC);
    cpa_wait1();
    __syncthreads();
    gemm128(sA, sW0, wm, wn, g, t4, qC);
    __syncthreads();
    stage_W(sW0, 2); cpa_commit();

    for (int r = 0; r < 5; ++r) {
        if (r < 4) cpa_wait1(); else cpa_wait0();
        __syncthreads();

        float kC[2][8][4]; ZERO_C(kC);
        gemm128(sA, sWb[(r + 1) & 1], wm, wn, g, t4, kC);

        // ---- logits, exp, E store, partial sums ----
        float hs0 = 0.f, hs1 = 0.f;
        #pragma unroll
        for (int mt = 0; mt < 2; ++mt) {
            #pragma unroll
            for (int rr = 0; rr < 2; ++rr) {
                int n = n0 + wm * 32 + mt * 16 + g + rr * 8;
                #pragma unroll
                for (int hl = 0; hl < 2; ++hl) {
                    float ds = 0.f;
                    #pragma unroll
                    for (int nt4 = 0; nt4 < 4; ++nt4) {
                        int nt = hl * 4 + nt4;
                        ds = fmaf(qC[mt][nt][rr * 2],     kC[mt][nt][rr * 2],     ds);
                        ds = fmaf(qC[mt][nt][rr * 2 + 1], kC[mt][nt][rr * 2 + 1], ds);
                    }
                    ds += __shfl_xor_sync(0xFFFFFFFFu, ds, 1);
                    ds += __shfl_xor_sync(0xFFFFFFFFu, ds, 2);
                    if (t4 == 0) {
                        float e = 0.f;
                        if (n < N) {
                            e = __expf(ds * SCALE);
                            g_E[(size_t)((wn * 2 + hl) * 5 + r) * N + n] = e;
                        }
                        if (hl == 0) hs0 += e; else hs1 += e;
                    }
                }
            }
        }
        #pragma unroll
        for (int o = 16; o > 0; o >>= 1) {
            hs0 += __shfl_down_sync(0xFFFFFFFFu, hs0, o);
            hs1 += __shfl_down_sync(0xFFFFFFFFu, hs1, o);
        }
        if (l == 0) { warr[w][0] = hs0; warr[w][1] = hs1; }
        __syncthreads();                  // GEMM smem reads done + warr visible
        if (t < 4) {
            int h = t;
            float s = 0.f;
            #pragma unroll
            for (int m = 0; m < 4; ++m) s += warr[m * 2 + (h >> 1)][h & 1];
            g_part[(h * 5 + r) * MAXTILES + tile] = s;
        }

        if (r + 1 < 5)  { stage_A(sA, x, nbr, is64, n0, r + 1, N); cpa_commit(); }
        if (r + 3 <= 5) { stage_W(sWb[(r + 1) & 1], r + 3); cpa_commit(); }
    }
}

// -------- kernel R --------
__global__ void knot_R(int cnt)
{
    __shared__ float smr[256];
    const int b = blockIdx.x;
    float s = 0.f;
    for (int i = threadIdx.x; i < cnt; i += 256) s += g_part[b * MAXTILES + i];
    smr[threadIdx.x] = s;
    __syncthreads();
    for (int off = 128; off > 0; off >>= 1) {
        if (threadIdx.x < off) smr[threadIdx.x] += smr[threadIdx.x + off];
        __syncthreads();
    }
    if (threadIdx.x == 0) g_Sinv[b] = 1.0f / smr[0];
}

// -------- kernel O --------
__global__ __launch_bounds__(THREADS, 1)
void knot_O(const float* __restrict__ x, const void* __restrict__ nbr,
            float* __restrict__ out, int N)
{
    extern __shared__ float smf[];
    float* sA  = smf;
    float* sW0 = smf + A_FLOATS;
    float* sW1 = sW0 + W_FLOATS;
    float* sWb[2] = { sW0, sW1 };

    const int t = threadIdx.x, w = t >> 5, l = t & 31;
    const int wm = w >> 1, wn = w & 1, g = l >> 2, t4 = l & 3;
    const int tile = blockIdx.x, n0 = tile * NT;
    const int is64 = g_is64;

    stage_W(sW0, 6); cpa_commit();
    stage_A(sA, x, nbr, is64, n0, 0, N); cpa_commit();
    stage_W(sW1, 7); cpa_commit();

    float acc[2][8][4]; ZERO_C(acc);

    for (int r = 0; r < 5; ++r) {
        if (r < 4) cpa_wait1(); else cpa_wait0();
        __syncthreads();

        float C[2][8][4]; ZERO_C(C);
        gemm128(sA, sWb[r & 1], wm, wn, g, t4, C);

        float av[2][2][2];   // [mt][rr][hl]
        #pragma unroll
        for (int mt = 0; mt < 2; ++mt)
            #pragma unroll
            for (int rr = 0; rr < 2; ++rr) {
                int n = n0 + wm * 32 + mt * 16 + g + rr * 8;
                #pragma unroll
                for (int hl = 0; hl < 2; ++hl) {
                    int h = wn * 2 + hl;
                    av[mt][rr][hl] = (n < N)
                        ? __ldg(&g_E[(size_t)(h * 5 + r) * N + n]) * g_Sinv[h * 5 + r]
                        : 0.f;
                }
            }
        #pragma unroll
        for (int mt = 0; mt < 2; ++mt)
            #pragma unroll
            for (int nt = 0; nt < 8; ++nt)
                #pragma unroll
                for (int ci = 0; ci < 4; ++ci)
                    acc[mt][nt][ci] = fmaf(av[mt][ci >> 1][nt >> 2], C[mt][nt][ci],
                                           acc[mt][nt][ci]);
        __syncthreads();                  // smem reads done before restage

        if (r + 1 <= 4) { stage_A(sA, x, nbr, is64, n0, r + 1, N); cpa_commit(); }
        if (r + 2 <= 4) { stage_W(sWb[r & 1], 6 + r + 2); cpa_commit(); }
    }

    // ---- transpose via smem (A region, 128 x AS_A), coalesced output ----
    #pragma unroll
    for (int mt = 0; mt < 2; ++mt)
        #pragma unroll
        for (int nt = 0; nt < 8; ++nt)
            #pragma unroll
            for (int ci = 0; ci < 4; ++ci) {
                int row = wm * 32 + mt * 16 + g + (ci >> 1) * 8;
                int col = wn * 64 + nt * 8 + t4 * 2 + (ci & 1);
                sA[row * AS_A + col] = acc[mt][nt][ci];
            }
    __syncthreads();
    #pragma unroll
    for (int i = 0; i < 16; ++i) {
        int f = t + 256 * i;
        int row = f >> 5, c4 = f & 31;
        int n = n0 + row;
        if (n < N)
            *(float4*)(out + (size_t)n * 128 + c4 * 4) =
                *(const float4*)(sA + row * AS_A + c4 * 4);
    }
}

extern "C" void kernel_launch(void* const* d_in, const int* in_sizes, int n_in,
                              void* d_out, int out_size)
{
    const float* x   = (const float*)d_in[0];
    const void*  nbr = d_in[1];
    const float* wq  = (const float*)d_in[2];
    const float* wk  = (const float*)d_in[3];
    const float* wv  = (const float*)d_in[4];
    float*       out = (float*)d_out;

    const int N   = in_sizes[0] / 128;
    const int NBT = (N + NT - 1) / NT;

    cudaFuncSetAttribute(knot_E, cudaFuncAttributeMaxDynamicSharedMemorySize, SMEM_SZ);
    cudaFuncSetAttribute(knot_O, cudaFuncAttributeMaxDynamicSharedMemorySize, SMEM_SZ);

    knot_detect<<<1, 32>>>((const int*)nbr);
    knot_prep<<<11, 256>>>(wq, wk, wv);
    knot_E<<<NBT, THREADS, SMEM_SZ>>>(x, nbr, N);
    knot_R<<<20, 256>>>(NBT);
    knot_O<<<NBT, THREADS, SMEM_SZ>>>(x, nbr, out, N);
}

// round 8
// speedup vs baseline: 1.9279x; 1.5622x over previous
#include <cuda_runtime.h>
#include <cuda_fp16.h>
#include <math.h>
#include <stdint.h>

// ===========================================================================
// KnotAttention via mma.sync m16n8k16 fp16 (fp32 accum). NT=64 tiles,
// 2 CTAs/SM, double-buffered W cp.async pipeline, perm16 k-interleave so all
// A/B fragments are conflict-free LDS.64.
//  prep_x: x -> fp16, k-permuted          prep_w: W -> [slot][n][perm16(d)] fp16
//  E: per tile: Q=A0@Wq; per r: K_r=A_r@Wk_r; E=exp(QK/sqrt32); partials
//  R: reduce partials -> 1/denominator (softmax over NODE axis)
//  O: per r: V_r=A_r@Wv_r; acc += (E*Sinv)*V_r; write out
// ===========================================================================

#define NT       64
#define THREADS  256
#define MAXN     131072
#define MAXTILES (MAXN / NT)
#define SCALE    0.17677669529663687f   // 1/sqrt(32)
#define SH       144                    // smem row stride in halves (288B)
#define A_HALVES (NT * SH)              // 9216
#define W_HALVES (128 * SH)             // 18432
#define SMEM_SZ  ((A_HALVES + 2 * W_HALVES) * 2)   // 92160 B -> 2 CTAs/SM
#define AS_T     132                    // fp32 transpose stride (O epilogue)

__device__ float  g_E[(size_t)20 * MAXN];
__device__ float  g_part[20 * MAXTILES];
__device__ float  g_Sinv[20];
__device__ int    g_is64;
__device__ __half g_Wh[11 * 128 * 128];          // [slot][n][perm16(d)]
__device__ __half g_xh[(size_t)MAXN * 128];      // [n][perm16(d)]

// -------- helpers --------
__device__ __forceinline__ uint32_t smem_u32(const void* p) {
    uint32_t a;
    asm("{ .reg .u64 t; cvta.to.shared.u64 t, %1; cvt.u32.u64 %0, t; }" : "=r"(a) : "l"(p));
    return a;
}
__device__ __forceinline__ void cpa16(uint32_t s, const void* g) {
    asm volatile("cp.async.cg.shared.global [%0], [%1], 16;" :: "r"(s), "l"(g) : "memory");
}
__device__ __forceinline__ void cpa_commit() { asm volatile("cp.async.commit_group;" ::: "memory"); }
__device__ __forceinline__ void cpa_wait1()  { asm volatile("cp.async.wait_group 1;" ::: "memory"); }
__device__ __forceinline__ void cpa_wait0()  { asm volatile("cp.async.wait_group 0;" ::: "memory"); }

// interleave within 16-col groups so (2t4,2t4+1,2t4+8,2t4+9) are contiguous
__device__ __forceinline__ int perm16(int k) {
    int j = k & 15;
    int p = ((j >> 1) & 3) * 4 + (j & 1) + ((j >> 3) & 1) * 2;
    return (k & ~15) | p;
}

__device__ __forceinline__ void mma16816(float* c, uint32_t a0, uint32_t a1,
                                         uint32_t a2, uint32_t a3,
                                         uint32_t b0, uint32_t b1) {
    asm volatile(
        "mma.sync.aligned.m16n8k16.row.col.f32.f16.f16.f32 "
        "{%0,%1,%2,%3}, {%4,%5,%6,%7}, {%8,%9}, {%0,%1,%2,%3};"
        : "+f"(c[0]), "+f"(c[1]), "+f"(c[2]), "+f"(c[3])
        : "r"(a0), "r"(a1), "r"(a2), "r"(a3), "r"(b0), "r"(b1));
}

// -------- prep kernels --------
__global__ void knot_prep_x(const float* __restrict__ x, int total)
{
    for (int i = blockIdx.x * 256 + threadIdx.x; i < total; i += gridDim.x * 256) {
        int n = i >> 7, k = i & 127;
        g_xh[((size_t)n << 7) | perm16(k)] = __float2half_rn(x[i]);
    }
}
__global__ void knot_prep_w(const float* __restrict__ wq, const float* __restrict__ wk,
                            const float* __restrict__ wv)
{
    int slot = blockIdx.x;
    __half* dst = g_Wh + slot * 16384;
    for (int i = 0; i < 64; ++i) {
        int f = threadIdx.x + 256 * i;     // 0..16383
        int n = f >> 7, d = f & 127;
        int h = n >> 5, k = n & 31;
        float v;
        if (slot == 0)      v = wq[((size_t)h * 128 + d) * 32 + k];
        else if (slot <= 5) v = wk[(((size_t)(h * 5 + (slot - 1)) * 128) + d) * 32 + k];
        else                v = wv[(((size_t)(h * 5 + (slot - 6)) * 128) + d) * 32 + k];
        dst[n * 128 + perm16(d)] = __float2half_rn(v);
    }
}
__global__ void knot_detect(const int* __restrict__ nbr_i32)
{
    if (threadIdx.x == 0 && blockIdx.x == 0) {
        int any = 0;
        #pragma unroll
        for (int i = 1; i < 64; i += 2) any |= nbr_i32[i];
        g_is64 = (any == 0) ? 1 : 0;
    }
}

// -------- staging (cp.async 16B) --------
__device__ __forceinline__ void stage_A(__half* sA, const void* __restrict__ nbr,
                                        int is64, int n0, int r, int N)
{
    int t = threadIdx.x;
    #pragma unroll
    for (int i = 0; i < 4; ++i) {
        int f = t + 256 * i;               // 64 rows x 16 chunks of 16B
        int row = f >> 4, c16 = f & 15;
        int n = n0 + row;
        int nc = (n < N) ? n : 0;
        long long src;
        if (r == 0) src = nc;
        else {
            long long e = (long long)nc * 4 + (r - 1);
            src = is64 ? __ldg((const long long*)nbr + e)
                       : (long long)__ldg((const int*)nbr + e);
        }
        if (src < 0) src = 0;
        if (src >= N) src = N - 1;
        cpa16(smem_u32(sA + row * SH + c16 * 8), g_xh + ((size_t)src << 7) + c16 * 8);
    }
}
__device__ __forceinline__ void stage_W(__half* sW, int slot)
{
    const __half* src = g_Wh + slot * 16384;
    int t = threadIdx.x;
    #pragma unroll
    for (int i = 0; i < 8; ++i) {
        int f = t + 256 * i;               // 128 rows x 16 chunks
        int row = f >> 4, c16 = f & 15;
        cpa16(smem_u32(sW + row * SH + c16 * 8), src + row * 128 + c16 * 8);
    }
}

// -------- warp GEMM: 32(m) x 32(n); wm=w>>2 (0..1), wn=w&3 (head) --------
__device__ __forceinline__ void gemm64h(const __half* sA, const __half* sW,
                                        int wm, int wn, int g, int t4,
                                        float C[2][4][4])
{
    #pragma unroll
    for (int ks = 0; ks < 8; ++ks) {
        uint2 lo[2], hi[2];
        #pragma unroll
        for (int mt = 0; mt < 2; ++mt) {
            const __half* ap = sA + (wm * 32 + mt * 16 + g) * SH + ks * 16 + t4 * 4;
            lo[mt] = *(const uint2*)ap;            // {a0, a2}
            hi[mt] = *(const uint2*)(ap + 8 * SH); // {a1, a3}
        }
        #pragma unroll
        for (int nt = 0; nt < 4; ++nt) {
            uint2 b = *(const uint2*)(sW + (wn * 32 + nt * 8 + g) * SH + ks * 16 + t4 * 4);
            mma16816(C[0][nt], lo[0].x, hi[0].x, lo[0].y, hi[0].y, b.x, b.y);
            mma16816(C[1][nt], lo[1].x, hi[1].x, lo[1].y, hi[1].y, b.x, b.y);
        }
    }
}

#define ZERO_C(C)                                                   \
    _Pragma("unroll") for (int mt = 0; mt < 2; ++mt)                \
    _Pragma("unroll") for (int nt = 0; nt < 4; ++nt)                \
    _Pragma("unroll") for (int ci = 0; ci < 4; ++ci) C[mt][nt][ci] = 0.f;

// -------- kernel E --------
__global__ __launch_bounds__(THREADS, 2)
void knot_E(const void* __restrict__ nbr, int N)
{
    extern __shared__ __align__(16) char smc[];
    __half* sA  = (__half*)smc;
    __half* sW0 = sA + A_HALVES;
    __half* sW1 = sW0 + W_HALVES;
    __half* sWb[2] = { sW0, sW1 };
    __shared__ float warr[8];

    const int t = threadIdx.x, w = t >> 5, l = t & 31;
    const int wm = w >> 2, wn = w & 3, g = l >> 2, t4 = l & 3;
    const int tile = blockIdx.x, n0 = tile * NT;
    const int is64 = g_is64;
    const int h = wn;

    // prologue: W0, A0, W1
    stage_W(sW0, 0); cpa_commit();
    stage_A(sA, nbr, is64, n0, 0, N); cpa_commit();
    stage_W(sW1, 1); cpa_commit();

    // ---- Q (buf0) ----
    float qC[2][4][4]; ZERO_C(qC);
    cpa_wait1();
    __syncthreads();
    gemm64h(sA, sW0, wm, wn, g, t4, qC);
    __syncthreads();
    stage_W(sW0, 2); cpa_commit();

    for (int r = 0; r < 5; ++r) {
        if (r < 4) cpa_wait1(); else cpa_wait0();
        __syncthreads();

        float kC[2][4][4]; ZERO_C(kC);
        gemm64h(sA, sWb[(r + 1) & 1], wm, wn, g, t4, kC);

        // ---- logits, exp, E store, partial sums (head h = wn) ----
        float hs = 0.f;
        #pragma unroll
        for (int mt = 0; mt < 2; ++mt) {
            #pragma unroll
            for (int rr2 = 0; rr2 < 2; ++rr2) {
                int n = n0 + wm * 32 + mt * 16 + g + rr2 * 8;
                float ds = 0.f;
                #pragma unroll
                for (int nt = 0; nt < 4; ++nt) {
                    ds = fmaf(qC[mt][nt][rr2 * 2],     kC[mt][nt][rr2 * 2],     ds);
                    ds = fmaf(qC[mt][nt][rr2 * 2 + 1], kC[mt][nt][rr2 * 2 + 1], ds);
                }
                ds += __shfl_xor_sync(0xFFFFFFFFu, ds, 1);
                ds += __shfl_xor_sync(0xFFFFFFFFu, ds, 2);
                if (t4 == 0) {
                    float e = 0.f;
                    if (n < N) {
                        e = __expf(ds * SCALE);
                        g_E[(size_t)(h * 5 + r) * N + n] = e;
                    }
                    hs += e;
                }
            }
        }
        #pragma unroll
        for (int o = 16; o > 0; o >>= 1)
            hs += __shfl_down_sync(0xFFFFFFFFu, hs, o);
        if (l == 0) warr[w] = hs;
        __syncthreads();                  // GEMM smem reads done + warr visible
        if (t < 4)
            g_part[(t * 5 + r) * MAXTILES + tile] = warr[t] + warr[4 + t];

        if (r + 1 < 5)  { stage_A(sA, nbr, is64, n0, r + 1, N); cpa_commit(); }
        if (r + 3 <= 5) { stage_W(sWb[(r + 1) & 1], r + 3); cpa_commit(); }
    }
}

// -------- kernel R --------
__global__ void knot_R(int cnt)
{
    __shared__ float smr[256];
    const int b = blockIdx.x;
    float s = 0.f;
    for (int i = threadIdx.x; i < cnt; i += 256) s += g_part[b * MAXTILES + i];
    smr[threadIdx.x] = s;
    __syncthreads();
    for (int off = 128; off > 0; off >>= 1) {
        if (threadIdx.x < off) smr[threadIdx.x] += smr[threadIdx.x + off];
        __syncthreads();
    }
    if (threadIdx.x == 0) g_Sinv[b] = 1.0f / smr[0];
}

// -------- kernel O --------
__global__ __launch_bounds__(THREADS, 2)
void knot_O(const void* __restrict__ nbr, float* __restrict__ out, int N)
{
    extern __shared__ __align__(16) char smc[];
    __half* sA  = (__half*)smc;
    __half* sW0 = sA + A_HALVES;
    __half* sW1 = sW0 + W_HALVES;
    __half* sWb[2] = { sW0, sW1 };

    const int t = threadIdx.x, w = t >> 5, l = t & 31;
    const int wm = w >> 2, wn = w & 3, g = l >> 2, t4 = l & 3;
    const int tile = blockIdx.x, n0 = tile * NT;
    const int is64 = g_is64;
    const int h = wn;

    stage_W(sW0, 6); cpa_commit();
    stage_A(sA, nbr, is64, n0, 0, N); cpa_commit();
    stage_W(sW1, 7); cpa_commit();

    float acc[2][4][4]; ZERO_C(acc);

    for (int r = 0; r < 5; ++r) {
        if (r < 4) cpa_wait1(); else cpa_wait0();
        __syncthreads();

        float C[2][4][4]; ZERO_C(C);
        gemm64h(sA, sWb[r & 1], wm, wn, g, t4, C);

        float av[2][2];
        const float si = g_Sinv[h * 5 + r];
        #pragma unroll
        for (int mt = 0; mt < 2; ++mt)
            #pragma unroll
            for (int rr2 = 0; rr2 < 2; ++rr2) {
                int n = n0 + wm * 32 + mt * 16 + g + rr2 * 8;
                av[mt][rr2] = (n < N)
                    ? __ldg(&g_E[(size_t)(h * 5 + r) * N + n]) * si : 0.f;
            }
        #pragma unroll
        for (int mt = 0; mt < 2; ++mt)
            #pragma unroll
            for (int nt = 0; nt < 4; ++nt)
                #pragma unroll
                for (int ci = 0; ci < 4; ++ci)
                    acc[mt][nt][ci] = fmaf(av[mt][ci >> 1], C[mt][nt][ci],
                                           acc[mt][nt][ci]);
        __syncthreads();                  // smem reads done before restage

        if (r + 1 <= 4) { stage_A(sA, nbr, is64, n0, r + 1, N); cpa_commit(); }
        if (r + 2 <= 4) { stage_W(sWb[r & 1], 6 + r + 2); cpa_commit(); }
    }

    // ---- transpose via smem (fp32 view of whole buffer), coalesced output ----
    float* sT = (float*)smc;              // 64 x AS_T floats = 33.8KB < 92KB
    #pragma unroll
    for (int mt = 0; mt < 2; ++mt)
        #pragma unroll
        for (int nt = 0; nt < 4; ++nt)
            #pragma unroll
            for (int ci = 0; ci < 4; ++ci) {
                int row = wm * 32 + mt * 16 + g + (ci >> 1) * 8;
                int col = wn * 32 + nt * 8 + t4 * 2 + (ci & 1);
                sT[row * AS_T + col] = acc[mt][nt][ci];
            }
    __syncthreads();
    #pragma unroll
    for (int i = 0; i < 8; ++i) {
        int f = t + 256 * i;
        int row = f >> 5, c4 = f & 31;
        int n = n0 + row;
        if (n < N)
            *(float4*)(out + (size_t)n * 128 + c4 * 4) =
                *(const float4*)(sT + row * AS_T + c4 * 4);
    }
}

extern "C" void kernel_launch(void* const* d_in, const int* in_sizes, int n_in,
                              void* d_out, int out_size)
{
    const float* x   = (const float*)d_in[0];
    const void*  nbr = d_in[1];
    const float* wq  = (const float*)d_in[2];
    const float* wk  = (const float*)d_in[3];
    const float* wv  = (const float*)d_in[4];
    float*       out = (float*)d_out;

    const int N   = in_sizes[0] / 128;
    const int NBT = (N + NT - 1) / NT;

    cudaFuncSetAttribute(knot_E, cudaFuncAttributeMaxDynamicSharedMemorySize, SMEM_SZ);
    cudaFuncSetAttribute(knot_O, cudaFuncAttributeMaxDynamicSharedMemorySize, SMEM_SZ);

    knot_detect<<<1, 32>>>((const int*)nbr);
    knot_prep_x<<<1024, 256>>>(x, N * 128);
    knot_prep_w<<<11, 256>>>(wq, wk, wv);
    knot_E<<<NBT, THREADS, SMEM_SZ>>>(nbr, N);
    knot_R<<<20, 256>>>(NBT);
    knot_O<<<NBT, THREADS, SMEM_SZ>>>(nbr, out, N);
}

// round 9
// speedup vs baseline: 1.9539x; 1.0135x over previous
#include <cuda_runtime.h>
#include <cuda_fp16.h>
#include <math.h>
#include <stdint.h>

// ===========================================================================
// KnotAttention via mma.sync m16n8k16 fp16 + ldmatrix fragments. NT=64 tiles,
// 2 CTAs/SM, double-buffered W cp.async pipeline, 272B rows (conflict-free
// LDSM phases: 272B = 68 words == 4 mod 32).
//  prep_x: x -> fp16 [n][k]          prep_w: W -> [slot][n][k] fp16
//  E: per tile: Q=A0@Wq; per r: K_r=A_r@Wk_r; E=exp(QK/sqrt32); partials
//  R: reduce partials -> 1/denominator (softmax over NODE axis)
//  O: per r: V_r=A_r@Wv_r; acc += (E*Sinv)*V_r; write out
// ===========================================================================

#define NT       64
#define THREADS  256
#define MAXN     131072
#define MAXTILES (MAXN / NT)
#define SCALE    0.17677669529663687f   // 1/sqrt(32)
#define SH       136                    // smem row stride in halves (272B)
#define ROWB     272                    // row stride bytes
#define A_HALVES (NT * SH)              // 8704
#define W_HALVES (128 * SH)             // 17408
#define SMEM_SZ  ((A_HALVES + 2 * W_HALVES) * 2)   // 87040 B -> 2 CTAs/SM
#define AS_T     132                    // fp32 transpose stride (O epilogue)

__device__ float  g_E[(size_t)20 * MAXN];
__device__ float  g_part[20 * MAXTILES];
__device__ float  g_Sinv[20];
__device__ int    g_is64;
__device__ __half g_Wh[11 * 128 * 128];          // [slot][n][k]
__device__ __half g_xh[(size_t)MAXN * 128];      // [n][k]

// -------- helpers --------
__device__ __forceinline__ uint32_t smem_u32(const void* p) {
    uint32_t a;
    asm("{ .reg .u64 t; cvta.to.shared.u64 t, %1; cvt.u32.u64 %0, t; }" : "=r"(a) : "l"(p));
    return a;
}
__device__ __forceinline__ void cpa16(uint32_t s, const void* g) {
    asm volatile("cp.async.cg.shared.global [%0], [%1], 16;" :: "r"(s), "l"(g) : "memory");
}
__device__ __forceinline__ void cpa_commit() { asm volatile("cp.async.commit_group;" ::: "memory"); }
__device__ __forceinline__ void cpa_wait1()  { asm volatile("cp.async.wait_group 1;" ::: "memory"); }
__device__ __forceinline__ void cpa_wait0()  { asm volatile("cp.async.wait_group 0;" ::: "memory"); }

__device__ __forceinline__ void ldsm4(uint32_t& r0, uint32_t& r1, uint32_t& r2,
                                      uint32_t& r3, uint32_t addr) {
    asm volatile("ldmatrix.sync.aligned.m8n8.x4.shared.b16 {%0,%1,%2,%3}, [%4];"
                 : "=r"(r0), "=r"(r1), "=r"(r2), "=r"(r3) : "r"(addr));
}
__device__ __forceinline__ void mma16816(float* c, uint32_t a0, uint32_t a1,
                                         uint32_t a2, uint32_t a3,
                                         uint32_t b0, uint32_t b1) {
    asm volatile(
        "mma.sync.aligned.m16n8k16.row.col.f32.f16.f16.f32 "
        "{%0,%1,%2,%3}, {%4,%5,%6,%7}, {%8,%9}, {%0,%1,%2,%3};"
        : "+f"(c[0]), "+f"(c[1]), "+f"(c[2]), "+f"(c[3])
        : "r"(a0), "r"(a1), "r"(a2), "r"(a3), "r"(b0), "r"(b1));
}

// -------- prep kernels (natural [n][k] layout) --------
__global__ void knot_prep_x(const float* __restrict__ x, int total)
{
    for (int i = blockIdx.x * 256 + threadIdx.x; i < total; i += gridDim.x * 256)
        g_xh[i] = __float2half_rn(x[i]);
}
__global__ void knot_prep_w(const float* __restrict__ wq, const float* __restrict__ wk,
                            const float* __restrict__ wv)
{
    int slot = blockIdx.x;
    __half* dst = g_Wh + slot * 16384;
    for (int i = 0; i < 64; ++i) {
        int f = threadIdx.x + 256 * i;     // 0..16383
        int n = f >> 7, d = f & 127;
        int h = n >> 5, k = n & 31;
        float v;
        if (slot == 0)      v = wq[((size_t)h * 128 + d) * 32 + k];
        else if (slot <= 5) v = wk[(((size_t)(h * 5 + (slot - 1)) * 128) + d) * 32 + k];
        else                v = wv[(((size_t)(h * 5 + (slot - 6)) * 128) + d) * 32 + k];
        dst[n * 128 + d] = __float2half_rn(v);
    }
}
__global__ void knot_detect(const int* __restrict__ nbr_i32)
{
    if (threadIdx.x == 0 && blockIdx.x == 0) {
        int any = 0;
        #pragma unroll
        for (int i = 1; i < 64; i += 2) any |= nbr_i32[i];
        g_is64 = (any == 0) ? 1 : 0;
    }
}

// -------- staging (cp.async 16B) --------
__device__ __forceinline__ void stage_A(__half* sA, const void* __restrict__ nbr,
                                        int is64, int n0, int r, int N)
{
    int t = threadIdx.x;
    #pragma unroll
    for (int i = 0; i < 4; ++i) {
        int f = t + 256 * i;               // 64 rows x 16 chunks of 16B
        int row = f >> 4, c16 = f & 15;
        int n = n0 + row;
        int nc = (n < N) ? n : 0;
        long long src;
        if (r == 0) src = nc;
        else {
            long long e = (long long)nc * 4 + (r - 1);
            src = is64 ? __ldg((const long long*)nbr + e)
                       : (long long)__ldg((const int*)nbr + e);
        }
        if (src < 0) src = 0;
        if (src >= N) src = N - 1;
        cpa16(smem_u32(sA + row * SH + c16 * 8), g_xh + ((size_t)src << 7) + c16 * 8);
    }
}
__device__ __forceinline__ void stage_W(__half* sW, int slot)
{
    const __half* src = g_Wh + slot * 16384;
    int t = threadIdx.x;
    #pragma unroll
    for (int i = 0; i < 8; ++i) {
        int f = t + 256 * i;               // 128 rows x 16 chunks
        int row = f >> 4, c16 = f & 15;
        cpa16(smem_u32(sW + row * SH + c16 * 8), src + row * 128 + c16 * 8);
    }
}

// -------- warp GEMM via ldmatrix: 32(m) x 32(n) per warp --------
// aAddr/bAddr: per-lane LDSM base addresses (lane j=l>>3, lr=l&7):
//   aAddr -> row (wm*32 + (j&1)*8 + lr), 16B chunk (j>>1)     [a0,a1,a2,a3]
//   bAddr -> row (wn*32 + (j>>1)*8 + lr), 16B chunk (j&1)     [b0,b1 x nt pair]
__device__ __forceinline__ void gemm64m(uint32_t aAddr, uint32_t bAddr,
                                        float C[2][4][4])
{
    #pragma unroll
    for (int ks = 0; ks < 8; ++ks) {
        uint32_t a0[4], a1[4], b0[4], b1[4];
        ldsm4(a0[0], a0[1], a0[2], a0[3], aAddr + ks * 32);
        ldsm4(a1[0], a1[1], a1[2], a1[3], aAddr + 16 * ROWB + ks * 32);
        ldsm4(b0[0], b0[1], b0[2], b0[3], bAddr + ks * 32);
        ldsm4(b1[0], b1[1], b1[2], b1[3], bAddr + 16 * ROWB + ks * 32);
        mma16816(C[0][0], a0[0], a0[1], a0[2], a0[3], b0[0], b0[1]);
        mma16816(C[0][1], a0[0], a0[1], a0[2], a0[3], b0[2], b0[3]);
        mma16816(C[0][2], a0[0], a0[1], a0[2], a0[3], b1[0], b1[1]);
        mma16816(C[0][3], a0[0], a0[1], a0[2], a0[3], b1[2], b1[3]);
        mma16816(C[1][0], a1[0], a1[1], a1[2], a1[3], b0[0], b0[1]);
        mma16816(C[1][1], a1[0], a1[1], a1[2], a1[3], b0[2], b0[3]);
        mma16816(C[1][2], a1[0], a1[1], a1[2], a1[3], b1[0], b1[1]);
        mma16816(C[1][3], a1[0], a1[1], a1[2], a1[3], b1[2], b1[3]);
    }
}

#define ZERO_C(C)                                                   \
    _Pragma("unroll") for (int mt = 0; mt < 2; ++mt)                \
    _Pragma("unroll") for (int nt = 0; nt < 4; ++nt)                \
    _Pragma("unroll") for (int ci = 0; ci < 4; ++ci) C[mt][nt][ci] = 0.f;

// -------- kernel E --------
__global__ __launch_bounds__(THREADS, 2)
void knot_E(const void* __restrict__ nbr, int N)
{
    extern __shared__ __align__(16) char smc[];
    __half* sA  = (__half*)smc;
    __half* sW0 = sA + A_HALVES;
    __half* sW1 = sW0 + W_HALVES;
    __shared__ float warr[8];

    const int t = threadIdx.x, w = t >> 5, l = t & 31;
    const int wm = w >> 2, wn = w & 3, g = l >> 2, t4 = l & 3;
    const int tile = blockIdx.x, n0 = tile * NT;
    const int is64 = g_is64;
    const int h = wn;

    // per-lane LDSM base addresses
    const int j = l >> 3, lr = l & 7;
    const uint32_t aAddr = smem_u32(sA) + (wm * 32 + (j & 1) * 8 + lr) * ROWB + (j >> 1) * 16;
    const uint32_t bOff  = (wn * 32 + (j >> 1) * 8 + lr) * ROWB + (j & 1) * 16;
    const uint32_t bA0 = smem_u32(sW0) + bOff, bA1 = smem_u32(sW1) + bOff;
    const uint32_t bAb[2] = { bA0, bA1 };

    // prologue: W0, A0, W1
    stage_W(sW0, 0); cpa_commit();
    stage_A(sA, nbr, is64, n0, 0, N); cpa_commit();
    stage_W(sW1, 1); cpa_commit();

    // ---- Q (buf0) ----
    float qC[2][4][4]; ZERO_C(qC);
    cpa_wait1();
    __syncthreads();
    gemm64m(aAddr, bA0, qC);
    __syncthreads();
    stage_W(sW0, 2); cpa_commit();

    for (int r = 0; r < 5; ++r) {
        if (r < 4) cpa_wait1(); else cpa_wait0();
        __syncthreads();

        float kC[2][4][4]; ZERO_C(kC);
        gemm64m(aAddr, bAb[(r + 1) & 1], kC);

        // ---- logits, exp, E store, partial sums (head h = wn) ----
        float hs = 0.f;
        #pragma unroll
        for (int mt = 0; mt < 2; ++mt) {
            #pragma unroll
            for (int rr2 = 0; rr2 < 2; ++rr2) {
                int n = n0 + wm * 32 + mt * 16 + g + rr2 * 8;
                float ds = 0.f;
                #pragma unroll
                for (int nt = 0; nt < 4; ++nt) {
                    ds = fmaf(qC[mt][nt][rr2 * 2],     kC[mt][nt][rr2 * 2],     ds);
                    ds = fmaf(qC[mt][nt][rr2 * 2 + 1], kC[mt][nt][rr2 * 2 + 1], ds);
                }
                ds += __shfl_xor_sync(0xFFFFFFFFu, ds, 1);
                ds += __shfl_xor_sync(0xFFFFFFFFu, ds, 2);
                if (t4 == 0) {
                    float e = 0.f;
                    if (n < N) {
                        e = __expf(ds * SCALE);
                        g_E[(size_t)(h * 5 + r) * N + n] = e;
                    }
                    hs += e;
                }
            }
        }
        #pragma unroll
        for (int o = 16; o > 0; o >>= 1)
            hs += __shfl_down_sync(0xFFFFFFFFu, hs, o);
        if (l == 0) warr[w] = hs;
        __syncthreads();                  // GEMM smem reads done + warr visible
        if (t < 4)
            g_part[(t * 5 + r) * MAXTILES + tile] = warr[t] + warr[4 + t];

        if (r + 1 < 5)  { stage_A(sA, nbr, is64, n0, r + 1, N); cpa_commit(); }
        if (r + 3 <= 5) { stage_W((r + 1) & 1 ? sW1 : sW0, r + 3); cpa_commit(); }
    }
}

// -------- kernel R --------
__global__ void knot_R(int cnt)
{
    __shared__ float smr[256];
    const int b = blockIdx.x;
    float s = 0.f;
    for (int i = threadIdx.x; i < cnt; i += 256) s += g_part[b * MAXTILES + i];
    smr[threadIdx.x] = s;
    __syncthreads();
    for (int off = 128; off > 0; off >>= 1) {
        if (threadIdx.x < off) smr[threadIdx.x] += smr[threadIdx.x + off];
        __syncthreads();
    }
    if (threadIdx.x == 0) g_Sinv[b] = 1.0f / smr[0];
}

// -------- kernel O --------
__global__ __launch_bounds__(THREADS, 2)
void knot_O(const void* __restrict__ nbr, float* __restrict__ out, int N)
{
    extern __shared__ __align__(16) char smc[];
    __half* sA  = (__half*)smc;
    __half* sW0 = sA + A_HALVES;
    __half* sW1 = sW0 + W_HALVES;

    const int t = threadIdx.x, w = t >> 5, l = t & 31;
    const int wm = w >> 2, wn = w & 3, g = l >> 2, t4 = l & 3;
    const int tile = blockIdx.x, n0 = tile * NT;
    const int is64 = g_is64;
    const int h = wn;

    const int j = l >> 3, lr = l & 7;
    const uint32_t aAddr = smem_u32(sA) + (wm * 32 + (j & 1) * 8 + lr) * ROWB + (j >> 1) * 16;
    const uint32_t bOff  = (wn * 32 + (j >> 1) * 8 + lr) * ROWB + (j & 1) * 16;
    const uint32_t bAb[2] = { smem_u32(sW0) + bOff, smem_u32(sW1) + bOff };

    stage_W(sW0, 6); cpa_commit();
    stage_A(sA, nbr, is64, n0, 0, N); cpa_commit();
    stage_W(sW1, 7); cpa_commit();

    float acc[2][4][4]; ZERO_C(acc);

    for (int r = 0; r < 5; ++r) {
        if (r < 4) cpa_wait1(); else cpa_wait0();
        __syncthreads();

        float C[2][4][4]; ZERO_C(C);
        gemm64m(aAddr, bAb[r & 1], C);

        float av[2][2];
        const float si = g_Sinv[h * 5 + r];
        #pragma unroll
        for (int mt = 0; mt < 2; ++mt)
            #pragma unroll
            for (int rr2 = 0; rr2 < 2; ++rr2) {
                int n = n0 + wm * 32 + mt * 16 + g + rr2 * 8;
                av[mt][rr2] = (n < N)
                    ? __ldg(&g_E[(size_t)(h * 5 + r) * N + n]) * si : 0.f;
            }
        #pragma unroll
        for (int mt = 0; mt < 2; ++mt)
            #pragma unroll
            for (int nt = 0; nt < 4; ++nt)
                #pragma unroll
                for (int ci = 0; ci < 4; ++ci)
                    acc[mt][nt][ci] = fmaf(av[mt][ci >> 1], C[mt][nt][ci],
                                           acc[mt][nt][ci]);
        __syncthreads();                  // smem reads done before restage

        if (r + 1 <= 4) { stage_A(sA, nbr, is64, n0, r + 1, N); cpa_commit(); }
        if (r + 2 <= 4) { stage_W(r & 1 ? sW1 : sW0, 6 + r + 2); cpa_commit(); }
    }

    // ---- transpose via smem (fp32 view), coalesced output ----
    float* sT = (float*)smc;              // 64 x AS_T floats = 33.8KB < 87KB
    #pragma unroll
    for (int mt = 0; mt < 2; ++mt)
        #pragma unroll
        for (int nt = 0; nt < 4; ++nt)
            #pragma unroll
            for (int ci = 0; ci < 4; ++ci) {
                int row = wm * 32 + mt * 16 + g + (ci >> 1) * 8;
                int col = wn * 32 + nt * 8 + t4 * 2 + (ci & 1);
                sT[row * AS_T + col] = acc[mt][nt][ci];
            }
    __syncthreads();
    #pragma unroll
    for (int i = 0; i < 8; ++i) {
        int f = t + 256 * i;
        int row = f >> 5, c4 = f & 31;
        int n = n0 + row;
        if (n < N)
            *(float4*)(out + (size_t)n * 128 + c4 * 4) =
                *(const float4*)(sT + row * AS_T + c4 * 4);
    }
}

extern "C" void kernel_launch(void* const* d_in, const int* in_sizes, int n_in,
                              void* d_out, int out_size)
{
    const float* x   = (const float*)d_in[0];
    const void*  nbr = d_in[1];
    const float* wq  = (const float*)d_in[2];
    const float* wk  = (const float*)d_in[3];
    const float* wv  = (const float*)d_in[4];
    float*       out = (float*)d_out;

    const int N   = in_sizes[0] / 128;
    const int NBT = (N + NT - 1) / NT;

    cudaFuncSetAttribute(knot_E, cudaFuncAttributeMaxDynamicSharedMemorySize, SMEM_SZ);
    cudaFuncSetAttribute(knot_O, cudaFuncAttributeMaxDynamicSharedMemorySize, SMEM_SZ);

    knot_detect<<<1, 32>>>((const int*)nbr);
    knot_prep_x<<<1024, 256>>>(x, N * 128);
    knot_prep_w<<<11, 256>>>(wq, wk, wv);
    knot_E<<<NBT, THREADS, SMEM_SZ>>>(nbr, N);
    knot_R<<<20, 256>>>(NBT);
    knot_O<<<NBT, THREADS, SMEM_SZ>>>(nbr, out, N);
}